// round 7
// baseline (speedup 1.0000x reference)
#include <cuda_runtime.h>
#include <cstdint>
#include <math.h>

// Problem constants
#define Bc   2
#define Sc   2048
#define Ec   1024
#define Hc   16
#define Dc   64
#define NTOK (Bc*Sc)          // 4096
#define ATT_SCALE 0.125f

// ---------------------------------------------------------------------------
// Scratch (static __device__ — no allocation allowed)
// ---------------------------------------------------------------------------
__device__ float g_q  [Bc*Sc*Ec];
__device__ float g_k  [Bc*Sc*Ec];
__device__ float g_v  [Bc*Sc*Ec];
__device__ float g_ctx[Bc*Sc*Ec];
// packed bf16x2 pair buffers (hi, lo): [rows][K/2]
__device__ uint32_t g_xh [NTOK*Ec/2];
__device__ uint32_t g_xl [NTOK*Ec/2];
__device__ uint32_t g_ch [NTOK*Ec/2];
__device__ uint32_t g_cl [NTOK*Ec/2];
__device__ uint32_t g_wqh[Ec*Ec/2];
__device__ uint32_t g_wql[Ec*Ec/2];
__device__ uint32_t g_wkh[Ec*Ec/2];
__device__ uint32_t g_wkl[Ec*Ec/2];
__device__ uint32_t g_wvh[Ec*Ec/2];
__device__ uint32_t g_wvl[Ec*Ec/2];
__device__ uint32_t g_woh[Ec*Ec/2];
__device__ uint32_t g_wol[Ec*Ec/2];

// ---------------------------------------------------------------------------
// bf16 helpers
// ---------------------------------------------------------------------------
__device__ __forceinline__ void split_pack(float v0, float v1, uint32_t& h, uint32_t& l) {
    const uint32_t u0 = __float_as_uint(v0);
    const uint32_t u1 = __float_as_uint(v1);
    uint32_t hp;
    asm("prmt.b32 %0, %1, %2, 0x7632;" : "=r"(hp) : "r"(u0), "r"(u1));
    const float l0 = v0 - __uint_as_float(u0 & 0xFFFF0000u);
    const float l1 = v1 - __uint_as_float(u1 & 0xFFFF0000u);
    uint32_t lp;
    asm("cvt.rn.bf16x2.f32 %0, %1, %2;" : "=r"(lp) : "f"(l1), "f"(l0));
    h = hp; l = lp;
}

__device__ __forceinline__ void mma_bf16(float* c, const uint32_t* a, const uint32_t* b) {
    asm volatile(
        "mma.sync.aligned.m16n8k16.row.col.f32.bf16.bf16.f32 "
        "{%0,%1,%2,%3}, {%4,%5,%6,%7}, {%8,%9}, {%0,%1,%2,%3};"
        : "+f"(c[0]), "+f"(c[1]), "+f"(c[2]), "+f"(c[3])
        : "r"(a[0]), "r"(a[1]), "r"(a[2]), "r"(a[3]), "r"(b[0]), "r"(b[1]));
}

__device__ __forceinline__ uint32_t smem_u32(const void* p) {
    uint32_t a;
    asm("{ .reg .u64 t; cvta.to.shared.u64 t, %1; cvt.u32.u64 %0, t; }"
        : "=r"(a) : "l"(p));
    return a;
}

// ---------------------------------------------------------------------------
// split kernel: fp32 -> packed bf16x2 (hi, lo) pair arrays
// ---------------------------------------------------------------------------
__global__ void __launch_bounds__(256) split_pairs(const float4* __restrict__ x,
                                                   uint2* __restrict__ hp,
                                                   uint2* __restrict__ lp, int n4) {
    const int i = blockIdx.x * 256 + threadIdx.x;
    if (i >= n4) return;
    float4 v = x[i];
    uint32_t h0, l0, h1, l1;
    split_pack(v.x, v.y, h0, l0);
    split_pack(v.z, v.w, h1, l1);
    hp[i] = make_uint2(h0, h1);
    lp[i] = make_uint2(l0, l1);
}

// ---------------------------------------------------------------------------
// 3xBF16 GEMM, cp.async double-buffered. Operands pre-split packed pairs.
// C[M,N] = A[M,K] @ W[N,K]^T. 128x128 tile, k-panel 32 (16 pairs), 256 thr.
// ---------------------------------------------------------------------------
#define GK   Ec
#define KP2  (GK/2)            // 512 pairs per row
#define PRS  20                // smem pair-row stride (conflict-free)
#define NPAN 32
#define ARRU (128*PRS)         // u32 per operand array
#define BUFU (4*ARRU)          // u32 per buffer (Ah,Al,Bh,Bl)
#define GEMM_SMEM (2*BUFU*4)   // 81920 B

__global__ void __launch_bounds__(256, 2) gemm3_ca(const uint32_t* __restrict__ Ahg,
                                                   const uint32_t* __restrict__ Alg,
                                                   const uint32_t* __restrict__ Bhg,
                                                   const uint32_t* __restrict__ Blg,
                                                   float* __restrict__ C) {
    extern __shared__ uint32_t smu[];
    const uint32_t sbase = smem_u32(smu);

    const int tid  = threadIdx.x;
    const int wid  = tid >> 5;
    const int lane = tid & 31;
    const int wm   = (wid & 1) * 64;
    const int wn   = (wid >> 1) * 32;
    const int m0   = blockIdx.y * 128;
    const int n0   = blockIdx.x * 128;
    const int lq   = lane >> 2;
    const int lr   = lane & 3;

    const uint32_t* gb[4] = { Ahg + (size_t)m0 * KP2, Alg + (size_t)m0 * KP2,
                              Bhg + (size_t)n0 * KP2, Blg + (size_t)n0 * KP2 };

    float acc[4][4][4];
    #pragma unroll
    for (int i = 0; i < 4; i++)
        #pragma unroll
        for (int j = 0; j < 4; j++)
            #pragma unroll
            for (int e = 0; e < 4; e++) acc[i][j][e] = 0.f;

    // stage panel p into buffer buf (issue cp.async, then commit)
    #define STAGE(p, buf) do {                                                  \
        const int _pb = (p) * 16;                                               \
        _Pragma("unroll")                                                       \
        for (int arr = 0; arr < 4; arr++) {                                     \
            _Pragma("unroll")                                                   \
            for (int j = 0; j < 2; j++) {                                       \
                const int i   = tid + j * 256;                                  \
                const int row = i >> 2;                                         \
                const int c   = (i & 3) * 4;                                    \
                const uint32_t* src = gb[arr] + (size_t)row * KP2 + _pb + c;    \
                const uint32_t dst = sbase +                                    \
                    (uint32_t)((buf) * BUFU + arr * ARRU + row * PRS + c) * 4;  \
                asm volatile("cp.async.ca.shared.global [%0], [%1], 16;"        \
                             :: "r"(dst), "l"(src));                            \
            }                                                                   \
        }                                                                       \
        asm volatile("cp.async.commit_group;" ::: "memory");                    \
    } while (0)

    STAGE(0, 0);

    for (int p = 0; p < NPAN; p++) {
        if (p + 1 < NPAN) {
            STAGE(p + 1, (p + 1) & 1);
            asm volatile("cp.async.wait_group 1;" ::: "memory");
        } else {
            asm volatile("cp.async.wait_group 0;" ::: "memory");
        }
        __syncthreads();

        const uint32_t* Ah = smu + (p & 1) * BUFU;
        const uint32_t* Al = Ah + ARRU;
        const uint32_t* Bh = Al + ARRU;
        const uint32_t* Bl = Bh + ARRU;

        #pragma unroll
        for (int s2 = 0; s2 < 2; s2++) {
            const int pb = s2 * 8;
            uint32_t ah[4][4], al[4][4];
            #pragma unroll
            for (int mt = 0; mt < 4; mt++) {
                const int b0 = (wm + mt * 16 + lq) * PRS + pb + lr;
                const int b1 = b0 + 8 * PRS;
                ah[mt][0] = Ah[b0]; ah[mt][1] = Ah[b1];
                ah[mt][2] = Ah[b0 + 4]; ah[mt][3] = Ah[b1 + 4];
                al[mt][0] = Al[b0]; al[mt][1] = Al[b1];
                al[mt][2] = Al[b0 + 4]; al[mt][3] = Al[b1 + 4];
            }
            #pragma unroll
            for (int nt = 0; nt < 4; nt++) {
                const int bb = (wn + nt * 8 + lq) * PRS + pb + lr;
                uint32_t bh[2], bl[2];
                bh[0] = Bh[bb]; bh[1] = Bh[bb + 4];
                bl[0] = Bl[bb]; bl[1] = Bl[bb + 4];
                #pragma unroll
                for (int mt = 0; mt < 4; mt++) {
                    mma_bf16(acc[mt][nt], ah[mt], bh);
                    mma_bf16(acc[mt][nt], ah[mt], bl);
                    mma_bf16(acc[mt][nt], al[mt], bh);
                }
            }
        }
        __syncthreads();
    }

    #pragma unroll
    for (int mt = 0; mt < 4; mt++) {
        const int r0 = m0 + wm + mt * 16 + lq;
        #pragma unroll
        for (int nt = 0; nt < 4; nt++) {
            const int cc = n0 + wn + nt * 8 + lr * 2;
            *(float2*)&C[(size_t)r0 * Ec + cc]       = make_float2(acc[mt][nt][0], acc[mt][nt][1]);
            *(float2*)&C[(size_t)(r0 + 8) * Ec + cc] = make_float2(acc[mt][nt][2], acc[mt][nt][3]);
        }
    }
}

// ---------------------------------------------------------------------------
// Flash attention, causal, 3xBF16 m16n8k16.  Br=128 q-rows/CTA, 256 threads,
// 8 warps (warp = 16 rows x full 64-key tile). Split-at-staging packed pairs.
// ---------------------------------------------------------------------------
#define PST 36
#define FA_SMEM ((2*128 + 4*64) * PST * 4)   // 73728 B -> 2 CTAs/SM

__global__ void __launch_bounds__(256, 2) flash_attn_mma(const float* __restrict__ Q,
                                                         const float* __restrict__ Kg,
                                                         const float* __restrict__ Vg,
                                                         float* __restrict__ Ctx) {
    extern __shared__ uint32_t smu[];
    uint32_t* Qh  = smu;                   // [128][PST]
    uint32_t* Ql  = Qh  + 128 * PST;
    uint32_t* Kh  = Ql  + 128 * PST;       // [64][PST]
    uint32_t* Kl  = Kh  + 64 * PST;
    uint32_t* Vth = Kl  + 64 * PST;        // [dim][key-pair]
    uint32_t* Vtl = Vth + 64 * PST;

    const int tid  = threadIdx.x;
    const int wid  = tid >> 5;
    const int lane = tid & 31;
    const int lq   = lane >> 2;
    const int lr   = lane & 3;
    const int wrow = wid * 16;

    const int qt = gridDim.x - 1 - blockIdx.x;   // long CTAs first
    const int h  = blockIdx.y;
    const int b  = blockIdx.z;
    const size_t base = (size_t)b * Sc * Ec + (size_t)h * Dc;
    const int rowbase = qt * 128;

    // stage Q (128 rows, split+packed)
    #pragma unroll
    for (int it = 0; it < 8; it++) {
        const int i  = tid + it * 256;
        const int r  = i >> 4;
        const int d0 = (i & 15) * 4;
        float4 v = *(const float4*)&Q[base + (size_t)(rowbase + r) * Ec + d0];
        uint32_t h0, l0, h1, l1;
        split_pack(v.x, v.y, h0, l0);
        split_pack(v.z, v.w, h1, l1);
        *(uint2*)&Qh[r * PST + (d0 >> 1)] = make_uint2(h0, h1);
        *(uint2*)&Ql[r * PST + (d0 >> 1)] = make_uint2(l0, l1);
    }

    float o[8][4];
    #pragma unroll
    for (int nt = 0; nt < 8; nt++)
        #pragma unroll
        for (int e = 0; e < 4; e++) o[nt][e] = 0.f;
    float mr0 = -1e30f, mr1 = -1e30f, lr0 = 0.f, lr1 = 0.f;

    const unsigned FM = 0xffffffffu;
    const int jtmax = 2 * qt + 1;

    for (int jt = 0; jt <= jtmax; jt++) {
        __syncthreads();
        // stage K (rowwise dim-pairs)
        #pragma unroll
        for (int it = 0; it < 4; it++) {
            const int i  = tid + it * 256;
            const int r  = i >> 4;
            const int d0 = (i & 15) * 4;
            float4 v = *(const float4*)&Kg[base + (size_t)(jt * 64 + r) * Ec + d0];
            uint32_t h0, l0, h1, l1;
            split_pack(v.x, v.y, h0, l0);
            split_pack(v.z, v.w, h1, l1);
            *(uint2*)&Kh[r * PST + (d0 >> 1)] = make_uint2(h0, h1);
            *(uint2*)&Kl[r * PST + (d0 >> 1)] = make_uint2(l0, l1);
        }
        // stage V transposed (key-pairs)
        #pragma unroll
        for (int it = 0; it < 2; it++) {
            const int i  = tid + it * 256;
            const int kp = i >> 4;
            const int d0 = (i & 15) * 4;
            const size_t g = base + (size_t)(jt * 64 + kp * 2) * Ec + d0;
            float4 v0 = *(const float4*)&Vg[g];
            float4 v1 = *(const float4*)&Vg[g + Ec];
            uint32_t hh, ll;
            split_pack(v0.x, v1.x, hh, ll); Vth[(d0+0)*PST + kp] = hh; Vtl[(d0+0)*PST + kp] = ll;
            split_pack(v0.y, v1.y, hh, ll); Vth[(d0+1)*PST + kp] = hh; Vtl[(d0+1)*PST + kp] = ll;
            split_pack(v0.z, v1.z, hh, ll); Vth[(d0+2)*PST + kp] = hh; Vtl[(d0+2)*PST + kp] = ll;
            split_pack(v0.w, v1.w, hh, ll); Vth[(d0+3)*PST + kp] = hh; Vtl[(d0+3)*PST + kp] = ll;
        }
        __syncthreads();

        // per-warp causal skip: this warp's rows end before this kv tile starts
        if (jt * 64 > rowbase + wrow + 15) continue;

        // S = Q @ K^T
        float s[8][4];
        #pragma unroll
        for (int nt = 0; nt < 8; nt++)
            #pragma unroll
            for (int e = 0; e < 4; e++) s[nt][e] = 0.f;

        #pragma unroll
        for (int ks = 0; ks < 4; ks++) {
            const int pb = ks * 8;
            const int b0 = (wrow + lq) * PST + pb + lr;
            const int b1 = b0 + 8 * PST;
            uint32_t ah[4], al[4];
            ah[0] = Qh[b0]; ah[1] = Qh[b1]; ah[2] = Qh[b0 + 4]; ah[3] = Qh[b1 + 4];
            al[0] = Ql[b0]; al[1] = Ql[b1]; al[2] = Ql[b0 + 4]; al[3] = Ql[b1 + 4];
            #pragma unroll
            for (int nt = 0; nt < 8; nt++) {
                const int kb = (nt * 8 + lq) * PST + pb + lr;
                uint32_t bh[2], bl[2];
                bh[0] = Kh[kb]; bh[1] = Kh[kb + 4];
                bl[0] = Kl[kb]; bl[1] = Kl[kb + 4];
                mma_bf16(s[nt], ah, bh);
                mma_bf16(s[nt], ah, bl);
                mma_bf16(s[nt], al, bh);
            }
        }

        // scale + causal mask (global coords) when tile straddles the diagonal
        if (jt * 64 + 63 > rowbase + wrow) {
            const int row0 = rowbase + wrow + lq;
            const int row1 = row0 + 8;
            #pragma unroll
            for (int nt = 0; nt < 8; nt++) {
                const int c0 = jt * 64 + nt * 8 + lr * 2;
                s[nt][0] = (c0     > row0) ? -1e30f : s[nt][0] * ATT_SCALE;
                s[nt][1] = (c0 + 1 > row0) ? -1e30f : s[nt][1] * ATT_SCALE;
                s[nt][2] = (c0     > row1) ? -1e30f : s[nt][2] * ATT_SCALE;
                s[nt][3] = (c0 + 1 > row1) ? -1e30f : s[nt][3] * ATT_SCALE;
            }
        } else {
            #pragma unroll
            for (int nt = 0; nt < 8; nt++)
                #pragma unroll
                for (int e = 0; e < 4; e++) s[nt][e] *= ATT_SCALE;
        }

        // online softmax
        float mt0 = -1e30f, mt1 = -1e30f;
        #pragma unroll
        for (int nt = 0; nt < 8; nt++) {
            mt0 = fmaxf(mt0, fmaxf(s[nt][0], s[nt][1]));
            mt1 = fmaxf(mt1, fmaxf(s[nt][2], s[nt][3]));
        }
        mt0 = fmaxf(mt0, __shfl_xor_sync(FM, mt0, 1));
        mt0 = fmaxf(mt0, __shfl_xor_sync(FM, mt0, 2));
        mt1 = fmaxf(mt1, __shfl_xor_sync(FM, mt1, 1));
        mt1 = fmaxf(mt1, __shfl_xor_sync(FM, mt1, 2));
        const float mn0 = fmaxf(mr0, mt0);
        const float mn1 = fmaxf(mr1, mt1);
        const float a0 = __expf(mr0 - mn0);
        const float a1 = __expf(mr1 - mn1);
        float rs0 = 0.f, rs1 = 0.f;
        #pragma unroll
        for (int nt = 0; nt < 8; nt++) {
            s[nt][0] = __expf(s[nt][0] - mn0); rs0 += s[nt][0];
            s[nt][1] = __expf(s[nt][1] - mn0); rs0 += s[nt][1];
            s[nt][2] = __expf(s[nt][2] - mn1); rs1 += s[nt][2];
            s[nt][3] = __expf(s[nt][3] - mn1); rs1 += s[nt][3];
        }
        rs0 += __shfl_xor_sync(FM, rs0, 1);
        rs0 += __shfl_xor_sync(FM, rs0, 2);
        rs1 += __shfl_xor_sync(FM, rs1, 1);
        rs1 += __shfl_xor_sync(FM, rs1, 2);
        lr0 = lr0 * a0 + rs0; mr0 = mn0;
        lr1 = lr1 * a1 + rs1; mr1 = mn1;
        #pragma unroll
        for (int nt = 0; nt < 8; nt++) {
            o[nt][0] *= a0; o[nt][1] *= a0;
            o[nt][2] *= a1; o[nt][3] *= a1;
        }

        // O += P @ V (P A-fragments straight from S registers)
        #pragma unroll
        for (int ks = 0; ks < 4; ks++) {
            uint32_t ph[4], pl[4];
            split_pack(s[2*ks][0],   s[2*ks][1],   ph[0], pl[0]);
            split_pack(s[2*ks][2],   s[2*ks][3],   ph[1], pl[1]);
            split_pack(s[2*ks+1][0], s[2*ks+1][1], ph[2], pl[2]);
            split_pack(s[2*ks+1][2], s[2*ks+1][3], ph[3], pl[3]);
            const int pb = ks * 8;
            #pragma unroll
            for (int nt = 0; nt < 8; nt++) {
                const int vb = (nt * 8 + lq) * PST + pb + lr;
                uint32_t vh[2], vl[2];
                vh[0] = Vth[vb]; vh[1] = Vth[vb + 4];
                vl[0] = Vtl[vb]; vl[1] = Vtl[vb + 4];
                mma_bf16(o[nt], ph, vh);
                mma_bf16(o[nt], ph, vl);
                mma_bf16(o[nt], pl, vh);
            }
        }
    }

    // epilogue
    const float inv0 = 1.0f / lr0;
    const float inv1 = 1.0f / lr1;
    const size_t ro0 = base + (size_t)(rowbase + wrow + lq) * Ec;
    const size_t ro1 = ro0 + 8 * (size_t)Ec;
    #pragma unroll
    for (int nt = 0; nt < 8; nt++) {
        const int cc = nt * 8 + lr * 2;
        *(float2*)&Ctx[ro0 + cc] = make_float2(o[nt][0] * inv0, o[nt][1] * inv0);
        *(float2*)&Ctx[ro1 + cc] = make_float2(o[nt][2] * inv1, o[nt][3] * inv1);
    }
}

// ---------------------------------------------------------------------------
extern "C" void kernel_launch(void* const* d_in, const int* in_sizes, int n_in,
                              void* d_out, int out_size) {
    (void)in_sizes; (void)n_in; (void)out_size;
    const float* x  = (const float*)d_in[0];
    const float* wq = (const float*)d_in[1];
    const float* wk = (const float*)d_in[2];
    const float* wv = (const float*)d_in[3];
    const float* wo = (const float*)d_in[4];
    float* out = (float*)d_out;

    float *q, *k, *v, *ctx;
    uint32_t *xh, *xl, *ch, *cl, *wqh, *wql, *wkh, *wkl, *wvh, *wvl, *woh, *wol;
    cudaGetSymbolAddress((void**)&q,   g_q);
    cudaGetSymbolAddress((void**)&k,   g_k);
    cudaGetSymbolAddress((void**)&v,   g_v);
    cudaGetSymbolAddress((void**)&ctx, g_ctx);
    cudaGetSymbolAddress((void**)&xh,  g_xh);
    cudaGetSymbolAddress((void**)&xl,  g_xl);
    cudaGetSymbolAddress((void**)&ch,  g_ch);
    cudaGetSymbolAddress((void**)&cl,  g_cl);
    cudaGetSymbolAddress((void**)&wqh, g_wqh);
    cudaGetSymbolAddress((void**)&wql, g_wql);
    cudaGetSymbolAddress((void**)&wkh, g_wkh);
    cudaGetSymbolAddress((void**)&wkl, g_wkl);
    cudaGetSymbolAddress((void**)&wvh, g_wvh);
    cudaGetSymbolAddress((void**)&wvl, g_wvl);
    cudaGetSymbolAddress((void**)&woh, g_woh);
    cudaGetSymbolAddress((void**)&wol, g_wol);

    const int nx4 = NTOK * Ec / 4;
    const int nw4 = Ec * Ec / 4;
    split_pairs<<<nx4 / 256, 256>>>((const float4*)x,  (uint2*)xh,  (uint2*)xl,  nx4);
    split_pairs<<<nw4 / 256, 256>>>((const float4*)wq, (uint2*)wqh, (uint2*)wql, nw4);
    split_pairs<<<nw4 / 256, 256>>>((const float4*)wk, (uint2*)wkh, (uint2*)wkl, nw4);
    split_pairs<<<nw4 / 256, 256>>>((const float4*)wv, (uint2*)wvh, (uint2*)wvl, nw4);
    split_pairs<<<nw4 / 256, 256>>>((const float4*)wo, (uint2*)woh, (uint2*)wol, nw4);

    cudaFuncSetAttribute(gemm3_ca, cudaFuncAttributeMaxDynamicSharedMemorySize, GEMM_SMEM);
    const dim3 ggrd(Ec / 128, NTOK / 128);
    gemm3_ca<<<ggrd, 256, GEMM_SMEM>>>(xh, xl, wqh, wql, q);
    gemm3_ca<<<ggrd, 256, GEMM_SMEM>>>(xh, xl, wkh, wkl, k);
    gemm3_ca<<<ggrd, 256, GEMM_SMEM>>>(xh, xl, wvh, wvl, v);

    cudaFuncSetAttribute(flash_attn_mma, cudaFuncAttributeMaxDynamicSharedMemorySize, FA_SMEM);
    flash_attn_mma<<<dim3(Sc / 128, Hc, Bc), 256, FA_SMEM>>>(q, k, v, ctx);

    split_pairs<<<nx4 / 256, 256>>>((const float4*)ctx, (uint2*)ch, (uint2*)cl, nx4);
    gemm3_ca<<<ggrd, 256, GEMM_SMEM>>>(ch, cl, woh, wol, out);
}

// round 8
// speedup vs baseline: 1.0471x; 1.0471x over previous
#include <cuda_runtime.h>
#include <cstdint>
#include <math.h>

// Problem constants
#define Bc   2
#define Sc   2048
#define Ec   1024
#define Hc   16
#define Dc   64
#define NTOK (Bc*Sc)          // 4096
#define ATT_SCALE 0.125f

// ---------------------------------------------------------------------------
// Scratch (static __device__ — no allocation allowed)
// ---------------------------------------------------------------------------
__device__ float g_q  [Bc*Sc*Ec];
__device__ float g_k  [Bc*Sc*Ec];
__device__ float g_v  [Bc*Sc*Ec];
__device__ float g_ctx[Bc*Sc*Ec];
// packed bf16x2 pair buffers (hi, lo): [rows][K/2]
__device__ uint32_t g_xh [NTOK*Ec/2];
__device__ uint32_t g_xl [NTOK*Ec/2];
__device__ uint32_t g_ch [NTOK*Ec/2];
__device__ uint32_t g_cl [NTOK*Ec/2];
__device__ uint32_t g_wqh[Ec*Ec/2];
__device__ uint32_t g_wql[Ec*Ec/2];
__device__ uint32_t g_wkh[Ec*Ec/2];
__device__ uint32_t g_wkl[Ec*Ec/2];
__device__ uint32_t g_wvh[Ec*Ec/2];
__device__ uint32_t g_wvl[Ec*Ec/2];
__device__ uint32_t g_woh[Ec*Ec/2];
__device__ uint32_t g_wol[Ec*Ec/2];

// ---------------------------------------------------------------------------
// helpers
// ---------------------------------------------------------------------------
__device__ __forceinline__ void split_pack(float v0, float v1, uint32_t& h, uint32_t& l) {
    const uint32_t u0 = __float_as_uint(v0);
    const uint32_t u1 = __float_as_uint(v1);
    uint32_t hp;
    asm("prmt.b32 %0, %1, %2, 0x7632;" : "=r"(hp) : "r"(u0), "r"(u1));
    const float l0 = v0 - __uint_as_float(u0 & 0xFFFF0000u);
    const float l1 = v1 - __uint_as_float(u1 & 0xFFFF0000u);
    uint32_t lp;
    asm("cvt.rn.bf16x2.f32 %0, %1, %2;" : "=r"(lp) : "f"(l1), "f"(l0));
    h = hp; l = lp;
}

__device__ __forceinline__ void mma_bf16(float* c, const uint32_t* a, const uint32_t* b) {
    asm volatile(
        "mma.sync.aligned.m16n8k16.row.col.f32.bf16.bf16.f32 "
        "{%0,%1,%2,%3}, {%4,%5,%6,%7}, {%8,%9}, {%0,%1,%2,%3};"
        : "+f"(c[0]), "+f"(c[1]), "+f"(c[2]), "+f"(c[3])
        : "r"(a[0]), "r"(a[1]), "r"(a[2]), "r"(a[3]), "r"(b[0]), "r"(b[1]));
}

#define LDM4(r, addr) \
    asm volatile("ldmatrix.sync.aligned.m8n8.x4.shared.b16 {%0,%1,%2,%3}, [%4];" \
        : "=r"((r)[0]), "=r"((r)[1]), "=r"((r)[2]), "=r"((r)[3]) : "r"(addr))

__device__ __forceinline__ uint32_t smem_u32(const void* p) {
    uint32_t a;
    asm("{ .reg .u64 t; cvta.to.shared.u64 t, %1; cvt.u32.u64 %0, t; }"
        : "=r"(a) : "l"(p));
    return a;
}

// ---------------------------------------------------------------------------
// split kernel: fp32 -> packed bf16x2 (hi, lo) pair arrays
// ---------------------------------------------------------------------------
__global__ void __launch_bounds__(256) split_pairs(const float4* __restrict__ x,
                                                   uint2* __restrict__ hp,
                                                   uint2* __restrict__ lp, int n4) {
    const int i = blockIdx.x * 256 + threadIdx.x;
    if (i >= n4) return;
    float4 v = x[i];
    uint32_t h0, l0, h1, l1;
    split_pack(v.x, v.y, h0, l0);
    split_pack(v.z, v.w, h1, l1);
    hp[i] = make_uint2(h0, h1);
    lp[i] = make_uint2(l0, l1);
}

// ---------------------------------------------------------------------------
// 3xBF16 GEMM: cp.async double-buffered + ldmatrix fragment loads.
// ---------------------------------------------------------------------------
#define GK   Ec
#define KP2  (GK/2)
#define PRS  20
#define NPAN 32
#define ARRU (128*PRS)
#define ARRB (ARRU*4)
#define BUFU (4*ARRU)
#define BUFB (BUFU*4)
#define GEMM_SMEM (2*BUFB)     // 81920 B

__global__ void __launch_bounds__(256, 2) gemm3_ca(const uint32_t* __restrict__ Ahg,
                                                   const uint32_t* __restrict__ Alg,
                                                   const uint32_t* __restrict__ Bhg,
                                                   const uint32_t* __restrict__ Blg,
                                                   float* __restrict__ C) {
    extern __shared__ uint32_t smu[];
    const uint32_t sb = smem_u32(smu);

    const int tid  = threadIdx.x;
    const int wid  = tid >> 5;
    const int lane = tid & 31;
    const int wm   = (wid & 1) * 64;
    const int wn   = (wid >> 1) * 32;
    const int m0   = blockIdx.y * 128;
    const int n0   = blockIdx.x * 128;
    const int lq   = lane >> 2;
    const int lr   = lane & 3;

    const uint32_t* gb[4] = { Ahg + (size_t)m0 * KP2, Alg + (size_t)m0 * KP2,
                              Bhg + (size_t)n0 * KP2, Blg + (size_t)n0 * KP2 };

    // ldmatrix lane-pattern byte offsets (within a buffer)
    const uint32_t aPat = (uint32_t)((wm + (lane & 15)) * PRS + (lane >> 4) * 4) * 4;
    const uint32_t bPat = 2 * ARRB +
        (uint32_t)((wn + (lane & 7) + ((lane >> 4) & 1) * 8) * PRS + ((lane >> 3) & 1) * 4) * 4;

    float acc[4][4][4];
    #pragma unroll
    for (int i = 0; i < 4; i++)
        #pragma unroll
        for (int j = 0; j < 4; j++)
            #pragma unroll
            for (int e = 0; e < 4; e++) acc[i][j][e] = 0.f;

    #define STAGE(p, buf) do {                                                  \
        const int _pb = (p) * 16;                                               \
        _Pragma("unroll")                                                       \
        for (int arr = 0; arr < 4; arr++) {                                     \
            _Pragma("unroll")                                                   \
            for (int j = 0; j < 2; j++) {                                       \
                const int i   = tid + j * 256;                                  \
                const int row = i >> 2;                                         \
                const int c   = (i & 3) * 4;                                    \
                const uint32_t* src = gb[arr] + (size_t)row * KP2 + _pb + c;    \
                const uint32_t dst = sb +                                       \
                    (uint32_t)((buf) * BUFU + arr * ARRU + row * PRS + c) * 4;  \
                asm volatile("cp.async.ca.shared.global [%0], [%1], 16;"        \
                             :: "r"(dst), "l"(src));                            \
            }                                                                   \
        }                                                                       \
        asm volatile("cp.async.commit_group;" ::: "memory");                    \
    } while (0)

    STAGE(0, 0);

    for (int p = 0; p < NPAN; p++) {
        if (p + 1 < NPAN) {
            STAGE(p + 1, (p + 1) & 1);
            asm volatile("cp.async.wait_group 1;" ::: "memory");
        } else {
            asm volatile("cp.async.wait_group 0;" ::: "memory");
        }
        __syncthreads();

        const uint32_t bufB = (uint32_t)(p & 1) * BUFB;

        #pragma unroll
        for (int s2 = 0; s2 < 2; s2++) {
            const uint32_t pbB = (uint32_t)s2 * 32;   // 8 pairs = 32 bytes
            uint32_t ah[4][4], al[4][4];
            const uint32_t aa = sb + bufB + aPat + pbB;
            #pragma unroll
            for (int mt = 0; mt < 4; mt++) {
                LDM4(ah[mt], aa + (uint32_t)(mt * 16 * PRS) * 4);
                LDM4(al[mt], aa + (uint32_t)(mt * 16 * PRS) * 4 + ARRB);
            }
            const uint32_t ba = sb + bufB + bPat + pbB;
            #pragma unroll
            for (int ntp = 0; ntp < 2; ntp++) {
                uint32_t bh[4], bl[4];
                LDM4(bh, ba + (uint32_t)(ntp * 16 * PRS) * 4);
                LDM4(bl, ba + (uint32_t)(ntp * 16 * PRS) * 4 + ARRB);
                #pragma unroll
                for (int mt = 0; mt < 4; mt++) {
                    mma_bf16(acc[mt][2*ntp],   ah[mt], bh);
                    mma_bf16(acc[mt][2*ntp],   ah[mt], bl);
                    mma_bf16(acc[mt][2*ntp],   al[mt], bh);
                    mma_bf16(acc[mt][2*ntp+1], ah[mt], bh + 2);
                    mma_bf16(acc[mt][2*ntp+1], ah[mt], bl + 2);
                    mma_bf16(acc[mt][2*ntp+1], al[mt], bh + 2);
                }
            }
        }
        __syncthreads();
    }

    #pragma unroll
    for (int mt = 0; mt < 4; mt++) {
        const int r0 = m0 + wm + mt * 16 + lq;
        #pragma unroll
        for (int nt = 0; nt < 4; nt++) {
            const int cc = n0 + wn + nt * 8 + lr * 2;
            *(float2*)&C[(size_t)r0 * Ec + cc]       = make_float2(acc[mt][nt][0], acc[mt][nt][1]);
            *(float2*)&C[(size_t)(r0 + 8) * Ec + cc] = make_float2(acc[mt][nt][2], acc[mt][nt][3]);
        }
    }
}

// ---------------------------------------------------------------------------
// Flash attention, causal, 3xBF16 m16n8k16.  Br=64, 128 thr, 4 CTAs/SM.
// Fragment loads via ldmatrix.x4.
// ---------------------------------------------------------------------------
#define PST 36
#define QLB ((uint32_t)(64*PST)*4)        // bytes per array
#define FA_SMEM (6 * 64 * PST * 4)        // 55296 B

__global__ void __launch_bounds__(128, 4) flash_attn_mma(const float* __restrict__ Q,
                                                         const float* __restrict__ Kg,
                                                         const float* __restrict__ Vg,
                                                         float* __restrict__ Ctx) {
    extern __shared__ uint32_t smu[];
    uint32_t* Qh  = smu;                  // [64][PST]
    uint32_t* Ql  = Qh  + 64 * PST;
    uint32_t* Kh  = Ql  + 64 * PST;
    uint32_t* Kl  = Kh  + 64 * PST;
    uint32_t* Vth = Kl  + 64 * PST;       // [dim][key-pair]
    uint32_t* Vtl = Vth + 64 * PST;
    const uint32_t sbq = smem_u32(smu);

    const int tid  = threadIdx.x;
    const int wid  = tid >> 5;
    const int lane = tid & 31;
    const int lq   = lane >> 2;
    const int lr   = lane & 3;
    const int wrow = wid * 16;

    const int qt = gridDim.x - 1 - blockIdx.x;
    const int h  = blockIdx.y;
    const int b  = blockIdx.z;
    const size_t base = (size_t)b * Sc * Ec + (size_t)h * Dc;

    // ldmatrix lane patterns (byte offsets)
    const uint32_t aPat = sbq +
        (uint32_t)((wrow + (lane & 15)) * PST + (lane >> 4) * 4) * 4;           // Qh base
    const uint32_t bPat =
        (uint32_t)(((lane & 7) + ((lane >> 4) & 1) * 8) * PST + ((lane >> 3) & 1) * 4) * 4;
    const uint32_t kPat = sbq + 2 * QLB + bPat;                                  // Kh base
    const uint32_t vPat = sbq + 4 * QLB + bPat;                                  // Vth base

    // stage Q (split+packed)
    #pragma unroll
    for (int it = 0; it < 8; it++) {
        const int i  = tid + it * 128;
        const int r  = i >> 4;
        const int d0 = (i & 15) * 4;
        float4 v = *(const float4*)&Q[base + (size_t)(qt * 64 + r) * Ec + d0];
        uint32_t h0, l0, h1, l1;
        split_pack(v.x, v.y, h0, l0);
        split_pack(v.z, v.w, h1, l1);
        *(uint2*)&Qh[r * PST + (d0 >> 1)] = make_uint2(h0, h1);
        *(uint2*)&Ql[r * PST + (d0 >> 1)] = make_uint2(l0, l1);
    }

    float o[8][4];
    #pragma unroll
    for (int nt = 0; nt < 8; nt++)
        #pragma unroll
        for (int e = 0; e < 4; e++) o[nt][e] = 0.f;
    float mr0 = -1e30f, mr1 = -1e30f, lr0 = 0.f, lr1 = 0.f;

    const unsigned FM = 0xffffffffu;

    for (int jt = 0; jt <= qt; jt++) {
        __syncthreads();
        // stage K rowwise (dim pairs)
        #pragma unroll
        for (int it = 0; it < 8; it++) {
            const int i  = tid + it * 128;
            const int r  = i >> 4;
            const int d0 = (i & 15) * 4;
            float4 v = *(const float4*)&Kg[base + (size_t)(jt * 64 + r) * Ec + d0];
            uint32_t h0, l0, h1, l1;
            split_pack(v.x, v.y, h0, l0);
            split_pack(v.z, v.w, h1, l1);
            *(uint2*)&Kh[r * PST + (d0 >> 1)] = make_uint2(h0, h1);
            *(uint2*)&Kl[r * PST + (d0 >> 1)] = make_uint2(l0, l1);
        }
        // stage V transposed (key pairs)
        #pragma unroll
        for (int it = 0; it < 4; it++) {
            const int i  = tid + it * 128;
            const int kp = i >> 4;
            const int d0 = (i & 15) * 4;
            const size_t g = base + (size_t)(jt * 64 + kp * 2) * Ec + d0;
            float4 v0 = *(const float4*)&Vg[g];
            float4 v1 = *(const float4*)&Vg[g + Ec];
            uint32_t hh, ll;
            split_pack(v0.x, v1.x, hh, ll); Vth[(d0+0)*PST + kp] = hh; Vtl[(d0+0)*PST + kp] = ll;
            split_pack(v0.y, v1.y, hh, ll); Vth[(d0+1)*PST + kp] = hh; Vtl[(d0+1)*PST + kp] = ll;
            split_pack(v0.z, v1.z, hh, ll); Vth[(d0+2)*PST + kp] = hh; Vtl[(d0+2)*PST + kp] = ll;
            split_pack(v0.w, v1.w, hh, ll); Vth[(d0+3)*PST + kp] = hh; Vtl[(d0+3)*PST + kp] = ll;
        }
        __syncthreads();

        // S = Q @ K^T
        float s[8][4];
        #pragma unroll
        for (int nt = 0; nt < 8; nt++)
            #pragma unroll
            for (int e = 0; e < 4; e++) s[nt][e] = 0.f;

        #pragma unroll
        for (int ks = 0; ks < 4; ks++) {
            const uint32_t pbB = (uint32_t)ks * 32;
            uint32_t ah[4], al[4];
            LDM4(ah, aPat + pbB);
            LDM4(al, aPat + QLB + pbB);
            #pragma unroll
            for (int ntp = 0; ntp < 4; ntp++) {
                const uint32_t ka = kPat + (uint32_t)(ntp * 16 * PST) * 4 + pbB;
                uint32_t bh[4], bl[4];
                LDM4(bh, ka);
                LDM4(bl, ka + QLB);
                mma_bf16(s[2*ntp],   ah, bh);
                mma_bf16(s[2*ntp],   ah, bl);
                mma_bf16(s[2*ntp],   al, bh);
                mma_bf16(s[2*ntp+1], ah, bh + 2);
                mma_bf16(s[2*ntp+1], ah, bl + 2);
                mma_bf16(s[2*ntp+1], al, bh + 2);
            }
        }

        // scale + causal mask on diagonal tile
        if (jt == qt) {
            const int row0 = wrow + lq, row1 = wrow + lq + 8;
            #pragma unroll
            for (int nt = 0; nt < 8; nt++) {
                const int c0 = nt * 8 + lr * 2;
                s[nt][0] = (c0     > row0) ? -1e30f : s[nt][0] * ATT_SCALE;
                s[nt][1] = (c0 + 1 > row0) ? -1e30f : s[nt][1] * ATT_SCALE;
                s[nt][2] = (c0     > row1) ? -1e30f : s[nt][2] * ATT_SCALE;
                s[nt][3] = (c0 + 1 > row1) ? -1e30f : s[nt][3] * ATT_SCALE;
            }
        } else {
            #pragma unroll
            for (int nt = 0; nt < 8; nt++)
                #pragma unroll
                for (int e = 0; e < 4; e++) s[nt][e] *= ATT_SCALE;
        }

        // online softmax
        float mt0 = -1e30f, mt1 = -1e30f;
        #pragma unroll
        for (int nt = 0; nt < 8; nt++) {
            mt0 = fmaxf(mt0, fmaxf(s[nt][0], s[nt][1]));
            mt1 = fmaxf(mt1, fmaxf(s[nt][2], s[nt][3]));
        }
        mt0 = fmaxf(mt0, __shfl_xor_sync(FM, mt0, 1));
        mt0 = fmaxf(mt0, __shfl_xor_sync(FM, mt0, 2));
        mt1 = fmaxf(mt1, __shfl_xor_sync(FM, mt1, 1));
        mt1 = fmaxf(mt1, __shfl_xor_sync(FM, mt1, 2));
        const float mn0 = fmaxf(mr0, mt0);
        const float mn1 = fmaxf(mr1, mt1);
        const float a0 = __expf(mr0 - mn0);
        const float a1 = __expf(mr1 - mn1);
        float rs0 = 0.f, rs1 = 0.f;
        #pragma unroll
        for (int nt = 0; nt < 8; nt++) {
            s[nt][0] = __expf(s[nt][0] - mn0); rs0 += s[nt][0];
            s[nt][1] = __expf(s[nt][1] - mn0); rs0 += s[nt][1];
            s[nt][2] = __expf(s[nt][2] - mn1); rs1 += s[nt][2];
            s[nt][3] = __expf(s[nt][3] - mn1); rs1 += s[nt][3];
        }
        rs0 += __shfl_xor_sync(FM, rs0, 1);
        rs0 += __shfl_xor_sync(FM, rs0, 2);
        rs1 += __shfl_xor_sync(FM, rs1, 1);
        rs1 += __shfl_xor_sync(FM, rs1, 2);
        lr0 = lr0 * a0 + rs0; mr0 = mn0;
        lr1 = lr1 * a1 + rs1; mr1 = mn1;
        #pragma unroll
        for (int nt = 0; nt < 8; nt++) {
            o[nt][0] *= a0; o[nt][1] *= a0;
            o[nt][2] *= a1; o[nt][3] *= a1;
        }

        // O += P @ V (P A-fragments straight from S registers)
        #pragma unroll
        for (int ks = 0; ks < 4; ks++) {
            uint32_t ph[4], pl[4];
            split_pack(s[2*ks][0],   s[2*ks][1],   ph[0], pl[0]);
            split_pack(s[2*ks][2],   s[2*ks][3],   ph[1], pl[1]);
            split_pack(s[2*ks+1][0], s[2*ks+1][1], ph[2], pl[2]);
            split_pack(s[2*ks+1][2], s[2*ks+1][3], ph[3], pl[3]);
            const uint32_t pbB = (uint32_t)ks * 32;
            #pragma unroll
            for (int ntp = 0; ntp < 4; ntp++) {
                const uint32_t va = vPat + (uint32_t)(ntp * 16 * PST) * 4 + pbB;
                uint32_t vh[4], vl[4];
                LDM4(vh, va);
                LDM4(vl, va + QLB);
                mma_bf16(o[2*ntp],   ph, vh);
                mma_bf16(o[2*ntp],   ph, vl);
                mma_bf16(o[2*ntp],   pl, vh);
                mma_bf16(o[2*ntp+1], ph, vh + 2);
                mma_bf16(o[2*ntp+1], ph, vl + 2);
                mma_bf16(o[2*ntp+1], pl, vh + 2);
            }
        }
    }

    // epilogue
    const float inv0 = 1.0f / lr0;
    const float inv1 = 1.0f / lr1;
    const size_t ro0 = base + (size_t)(qt * 64 + wrow + lq) * Ec;
    const size_t ro1 = ro0 + 8 * (size_t)Ec;
    #pragma unroll
    for (int nt = 0; nt < 8; nt++) {
        const int cc = nt * 8 + lr * 2;
        *(float2*)&Ctx[ro0 + cc] = make_float2(o[nt][0] * inv0, o[nt][1] * inv0);
        *(float2*)&Ctx[ro1 + cc] = make_float2(o[nt][2] * inv1, o[nt][3] * inv1);
    }
}

// ---------------------------------------------------------------------------
extern "C" void kernel_launch(void* const* d_in, const int* in_sizes, int n_in,
                              void* d_out, int out_size) {
    (void)in_sizes; (void)n_in; (void)out_size;
    const float* x  = (const float*)d_in[0];
    const float* wq = (const float*)d_in[1];
    const float* wk = (const float*)d_in[2];
    const float* wv = (const float*)d_in[3];
    const float* wo = (const float*)d_in[4];
    float* out = (float*)d_out;

    float *q, *k, *v, *ctx;
    uint32_t *xh, *xl, *ch, *cl, *wqh, *wql, *wkh, *wkl, *wvh, *wvl, *woh, *wol;
    cudaGetSymbolAddress((void**)&q,   g_q);
    cudaGetSymbolAddress((void**)&k,   g_k);
    cudaGetSymbolAddress((void**)&v,   g_v);
    cudaGetSymbolAddress((void**)&ctx, g_ctx);
    cudaGetSymbolAddress((void**)&xh,  g_xh);
    cudaGetSymbolAddress((void**)&xl,  g_xl);
    cudaGetSymbolAddress((void**)&ch,  g_ch);
    cudaGetSymbolAddress((void**)&cl,  g_cl);
    cudaGetSymbolAddress((void**)&wqh, g_wqh);
    cudaGetSymbolAddress((void**)&wql, g_wql);
    cudaGetSymbolAddress((void**)&wkh, g_wkh);
    cudaGetSymbolAddress((void**)&wkl, g_wkl);
    cudaGetSymbolAddress((void**)&wvh, g_wvh);
    cudaGetSymbolAddress((void**)&wvl, g_wvl);
    cudaGetSymbolAddress((void**)&woh, g_woh);
    cudaGetSymbolAddress((void**)&wol, g_wol);

    const int nx4 = NTOK * Ec / 4;
    const int nw4 = Ec * Ec / 4;
    split_pairs<<<nx4 / 256, 256>>>((const float4*)x,  (uint2*)xh,  (uint2*)xl,  nx4);
    split_pairs<<<nw4 / 256, 256>>>((const float4*)wq, (uint2*)wqh, (uint2*)wql, nw4);
    split_pairs<<<nw4 / 256, 256>>>((const float4*)wk, (uint2*)wkh, (uint2*)wkl, nw4);
    split_pairs<<<nw4 / 256, 256>>>((const float4*)wv, (uint2*)wvh, (uint2*)wvl, nw4);
    split_pairs<<<nw4 / 256, 256>>>((const float4*)wo, (uint2*)woh, (uint2*)wol, nw4);

    cudaFuncSetAttribute(gemm3_ca, cudaFuncAttributeMaxDynamicSharedMemorySize, GEMM_SMEM);
    const dim3 ggrd(Ec / 128, NTOK / 128);
    gemm3_ca<<<ggrd, 256, GEMM_SMEM>>>(xh, xl, wqh, wql, q);
    gemm3_ca<<<ggrd, 256, GEMM_SMEM>>>(xh, xl, wkh, wkl, k);
    gemm3_ca<<<ggrd, 256, GEMM_SMEM>>>(xh, xl, wvh, wvl, v);

    cudaFuncSetAttribute(flash_attn_mma, cudaFuncAttributeMaxDynamicSharedMemorySize, FA_SMEM);
    flash_attn_mma<<<dim3(Sc / 64, Hc, Bc), 128, FA_SMEM>>>(q, k, v, ctx);

    split_pairs<<<nx4 / 256, 256>>>((const float4*)ctx, (uint2*)ch, (uint2*)cl, nx4);
    gemm3_ca<<<ggrd, 256, GEMM_SMEM>>>(ch, cl, woh, wol, out);
}

// round 9
// speedup vs baseline: 1.1982x; 1.1444x over previous
#include <cuda_runtime.h>
#include <cstdint>
#include <math.h>

// Problem constants
#define Bc   2
#define Sc   2048
#define Ec   1024
#define Hc   16
#define Dc   64
#define NTOK (Bc*Sc)          // 4096
#define ATT_SCALE 0.125f
#define KP2  (Ec/2)           // 512 pairs per row

// ---------------------------------------------------------------------------
// Scratch (static __device__ — no allocation allowed)
// packed bf16x2 pair buffers (hi, lo): [rows][K/2]
// ---------------------------------------------------------------------------
__device__ uint32_t g_xh [NTOK*KP2];
__device__ uint32_t g_xl [NTOK*KP2];
__device__ uint32_t g_qh [NTOK*KP2];
__device__ uint32_t g_ql [NTOK*KP2];
__device__ uint32_t g_kh [NTOK*KP2];
__device__ uint32_t g_kl [NTOK*KP2];
__device__ uint32_t g_vh [NTOK*KP2];
__device__ uint32_t g_vl [NTOK*KP2];
__device__ uint32_t g_ch [NTOK*KP2];
__device__ uint32_t g_cl [NTOK*KP2];
__device__ uint32_t g_wqh[Ec*KP2];
__device__ uint32_t g_wql[Ec*KP2];
__device__ uint32_t g_wkh[Ec*KP2];
__device__ uint32_t g_wkl[Ec*KP2];
__device__ uint32_t g_wvh[Ec*KP2];
__device__ uint32_t g_wvl[Ec*KP2];
__device__ uint32_t g_woh[Ec*KP2];
__device__ uint32_t g_wol[Ec*KP2];

// ---------------------------------------------------------------------------
// helpers
// ---------------------------------------------------------------------------
__device__ __forceinline__ void split_pack(float v0, float v1, uint32_t& h, uint32_t& l) {
    const uint32_t u0 = __float_as_uint(v0);
    const uint32_t u1 = __float_as_uint(v1);
    uint32_t hp;
    asm("prmt.b32 %0, %1, %2, 0x7632;" : "=r"(hp) : "r"(u0), "r"(u1));
    const float l0 = v0 - __uint_as_float(u0 & 0xFFFF0000u);
    const float l1 = v1 - __uint_as_float(u1 & 0xFFFF0000u);
    uint32_t lp;
    asm("cvt.rn.bf16x2.f32 %0, %1, %2;" : "=r"(lp) : "f"(l1), "f"(l0));
    h = hp; l = lp;
}

__device__ __forceinline__ void mma_bf16(float* c, const uint32_t* a, const uint32_t* b) {
    asm volatile(
        "mma.sync.aligned.m16n8k16.row.col.f32.bf16.bf16.f32 "
        "{%0,%1,%2,%3}, {%4,%5,%6,%7}, {%8,%9}, {%0,%1,%2,%3};"
        : "+f"(c[0]), "+f"(c[1]), "+f"(c[2]), "+f"(c[3])
        : "r"(a[0]), "r"(a[1]), "r"(a[2]), "r"(a[3]), "r"(b[0]), "r"(b[1]));
}

#define LDM4(r, addr) \
    asm volatile("ldmatrix.sync.aligned.m8n8.x4.shared.b16 {%0,%1,%2,%3}, [%4];" \
        : "=r"((r)[0]), "=r"((r)[1]), "=r"((r)[2]), "=r"((r)[3]) : "r"(addr))
#define LDM4T(r, addr) \
    asm volatile("ldmatrix.sync.aligned.m8n8.x4.trans.shared.b16 {%0,%1,%2,%3}, [%4];" \
        : "=r"((r)[0]), "=r"((r)[1]), "=r"((r)[2]), "=r"((r)[3]) : "r"(addr))
#define CPA16(dst, src) \
    asm volatile("cp.async.ca.shared.global [%0], [%1], 16;" :: "r"(dst), "l"(src))

__device__ __forceinline__ uint32_t smem_u32(const void* p) {
    uint32_t a;
    asm("{ .reg .u64 t; cvta.to.shared.u64 t, %1; cvt.u32.u64 %0, t; }"
        : "=r"(a) : "l"(p));
    return a;
}

// ---------------------------------------------------------------------------
// split kernel: fp32 -> packed bf16x2 (hi, lo) pair arrays (x + weights only)
// ---------------------------------------------------------------------------
__global__ void __launch_bounds__(256) split_pairs(const float4* __restrict__ x,
                                                   uint2* __restrict__ hp,
                                                   uint2* __restrict__ lp, int n4) {
    const int i = blockIdx.x * 256 + threadIdx.x;
    if (i >= n4) return;
    float4 v = x[i];
    uint32_t h0, l0, h1, l1;
    split_pack(v.x, v.y, h0, l0);
    split_pack(v.z, v.w, h1, l1);
    hp[i] = make_uint2(h0, h1);
    lp[i] = make_uint2(l0, l1);
}

// ---------------------------------------------------------------------------
// 3xBF16 GEMM core: cp.async double-buffered + ldmatrix.
// PAIR=true: writes split bf16x2 pair buffers.  PAIR=false: writes fp32.
// ---------------------------------------------------------------------------
#define PRS  20
#define NPAN 32
#define ARRU (128*PRS)
#define ARRB (ARRU*4)
#define BUFU (4*ARRU)
#define BUFB (BUFU*4)
#define GEMM_SMEM (2*BUFB)     // 81920 B

template<bool PAIR>
__device__ __forceinline__ void gemm_core(const uint32_t* __restrict__ Ahg,
                                          const uint32_t* __restrict__ Alg,
                                          const uint32_t* __restrict__ Bhg,
                                          const uint32_t* __restrict__ Blg,
                                          uint32_t* __restrict__ Oh,
                                          uint32_t* __restrict__ Ol,
                                          float* __restrict__ Cf) {
    extern __shared__ uint32_t smu[];
    const uint32_t sb = smem_u32(smu);

    const int tid  = threadIdx.x;
    const int wid  = tid >> 5;
    const int lane = tid & 31;
    const int wm   = (wid & 1) * 64;
    const int wn   = (wid >> 1) * 32;
    const int m0   = blockIdx.y * 128;
    const int n0   = blockIdx.x * 128;
    const int lq   = lane >> 2;
    const int lr   = lane & 3;

    const uint32_t* gb[4] = { Ahg + (size_t)m0 * KP2, Alg + (size_t)m0 * KP2,
                              Bhg + (size_t)n0 * KP2, Blg + (size_t)n0 * KP2 };

    const uint32_t aPat = (uint32_t)((wm + (lane & 15)) * PRS + (lane >> 4) * 4) * 4;
    const uint32_t bPat = 2 * ARRB +
        (uint32_t)((wn + (lane & 7) + ((lane >> 4) & 1) * 8) * PRS + ((lane >> 3) & 1) * 4) * 4;

    float acc[4][4][4];
    #pragma unroll
    for (int i = 0; i < 4; i++)
        #pragma unroll
        for (int j = 0; j < 4; j++)
            #pragma unroll
            for (int e = 0; e < 4; e++) acc[i][j][e] = 0.f;

    #define STAGE(p, buf) do {                                                  \
        const int _pb = (p) * 16;                                               \
        _Pragma("unroll")                                                       \
        for (int arr = 0; arr < 4; arr++) {                                     \
            _Pragma("unroll")                                                   \
            for (int j = 0; j < 2; j++) {                                       \
                const int i   = tid + j * 256;                                  \
                const int row = i >> 2;                                         \
                const int c   = (i & 3) * 4;                                    \
                const uint32_t* src = gb[arr] + (size_t)row * KP2 + _pb + c;    \
                const uint32_t dst = sb +                                       \
                    (uint32_t)((buf) * BUFU + arr * ARRU + row * PRS + c) * 4;  \
                CPA16(dst, src);                                                \
            }                                                                   \
        }                                                                       \
        asm volatile("cp.async.commit_group;" ::: "memory");                    \
    } while (0)

    STAGE(0, 0);

    for (int p = 0; p < NPAN; p++) {
        if (p + 1 < NPAN) {
            STAGE(p + 1, (p + 1) & 1);
            asm volatile("cp.async.wait_group 1;" ::: "memory");
        } else {
            asm volatile("cp.async.wait_group 0;" ::: "memory");
        }
        __syncthreads();

        const uint32_t bufB = (uint32_t)(p & 1) * BUFB;

        #pragma unroll
        for (int s2 = 0; s2 < 2; s2++) {
            const uint32_t pbB = (uint32_t)s2 * 32;
            uint32_t ah[4][4], al[4][4];
            const uint32_t aa = sb + bufB + aPat + pbB;
            #pragma unroll
            for (int mt = 0; mt < 4; mt++) {
                LDM4(ah[mt], aa + (uint32_t)(mt * 16 * PRS) * 4);
                LDM4(al[mt], aa + (uint32_t)(mt * 16 * PRS) * 4 + ARRB);
            }
            const uint32_t ba = sb + bufB + bPat + pbB;
            #pragma unroll
            for (int ntp = 0; ntp < 2; ntp++) {
                uint32_t bh[4], bl[4];
                LDM4(bh, ba + (uint32_t)(ntp * 16 * PRS) * 4);
                LDM4(bl, ba + (uint32_t)(ntp * 16 * PRS) * 4 + ARRB);
                #pragma unroll
                for (int mt = 0; mt < 4; mt++) {
                    mma_bf16(acc[mt][2*ntp],   ah[mt], bh);
                    mma_bf16(acc[mt][2*ntp],   ah[mt], bl);
                    mma_bf16(acc[mt][2*ntp],   al[mt], bh);
                    mma_bf16(acc[mt][2*ntp+1], ah[mt], bh + 2);
                    mma_bf16(acc[mt][2*ntp+1], ah[mt], bl + 2);
                    mma_bf16(acc[mt][2*ntp+1], al[mt], bh + 2);
                }
            }
        }
        __syncthreads();
    }

    #pragma unroll
    for (int mt = 0; mt < 4; mt++) {
        const int r0 = m0 + wm + mt * 16 + lq;
        #pragma unroll
        for (int nt = 0; nt < 4; nt++) {
            if (PAIR) {
                const int pidx = ((n0 + wn + nt * 8) >> 1) + lr;
                uint32_t h, l;
                split_pack(acc[mt][nt][0], acc[mt][nt][1], h, l);
                Oh[(size_t)r0 * KP2 + pidx] = h;
                Ol[(size_t)r0 * KP2 + pidx] = l;
                split_pack(acc[mt][nt][2], acc[mt][nt][3], h, l);
                Oh[(size_t)(r0 + 8) * KP2 + pidx] = h;
                Ol[(size_t)(r0 + 8) * KP2 + pidx] = l;
            } else {
                const int cc = n0 + wn + nt * 8 + lr * 2;
                *(float2*)&Cf[(size_t)r0 * Ec + cc]       = make_float2(acc[mt][nt][0], acc[mt][nt][1]);
                *(float2*)&Cf[(size_t)(r0 + 8) * Ec + cc] = make_float2(acc[mt][nt][2], acc[mt][nt][3]);
            }
        }
    }
}

// fused QKV (grid.z selects weight/output), pair output
__global__ void __launch_bounds__(256, 2) gemm_qkv(
    const uint32_t* __restrict__ xh,  const uint32_t* __restrict__ xl,
    const uint32_t* __restrict__ wqh, const uint32_t* __restrict__ wql,
    const uint32_t* __restrict__ wkh, const uint32_t* __restrict__ wkl,
    const uint32_t* __restrict__ wvh, const uint32_t* __restrict__ wvl,
    uint32_t* __restrict__ qh, uint32_t* __restrict__ ql,
    uint32_t* __restrict__ kh, uint32_t* __restrict__ kl,
    uint32_t* __restrict__ vh, uint32_t* __restrict__ vl) {
    const uint32_t *bh, *bl;
    uint32_t *oh, *ol;
    if (blockIdx.z == 0)      { bh = wqh; bl = wql; oh = qh; ol = ql; }
    else if (blockIdx.z == 1) { bh = wkh; bl = wkl; oh = kh; ol = kl; }
    else                      { bh = wvh; bl = wvl; oh = vh; ol = vl; }
    gemm_core<true>(xh, xl, bh, bl, oh, ol, nullptr);
}

// output projection, fp32 out
__global__ void __launch_bounds__(256, 2) gemm_wo(
    const uint32_t* __restrict__ ch, const uint32_t* __restrict__ cl,
    const uint32_t* __restrict__ woh, const uint32_t* __restrict__ wol,
    float* __restrict__ out) {
    gemm_core<false>(ch, cl, woh, wol, nullptr, nullptr, out);
}

// ---------------------------------------------------------------------------
// Flash attention, causal, 3xBF16 m16n8k16. Br=64, 128 thr, 4 CTAs/SM.
// Inputs are pre-split packed pair buffers; staging = pure cp.async copies.
// PV B-fragments via ldmatrix.trans on row-major V (no transpose staging).
// Epilogue emits split pairs for the WO GEMM.
// ---------------------------------------------------------------------------
#define PST 36
#define QLB ((uint32_t)(64*PST)*4)        // bytes per array
#define FA_SMEM (6 * 64 * PST * 4)        // 55296 B

__global__ void __launch_bounds__(128, 4) flash_attn_mma(
    const uint32_t* __restrict__ Qh, const uint32_t* __restrict__ Ql,
    const uint32_t* __restrict__ Kh, const uint32_t* __restrict__ Kl,
    const uint32_t* __restrict__ Vh, const uint32_t* __restrict__ Vl,
    uint32_t* __restrict__ Ch, uint32_t* __restrict__ Cl) {
    extern __shared__ uint32_t smu[];
    const uint32_t sbq = smem_u32(smu);

    const int tid  = threadIdx.x;
    const int wid  = tid >> 5;
    const int lane = tid & 31;
    const int lq   = lane >> 2;
    const int lr   = lane & 3;
    const int wrow = wid * 16;

    const int qt = gridDim.x - 1 - blockIdx.x;
    const int h  = blockIdx.y;
    const int b  = blockIdx.z;
    const int hb = h * 32;                         // pair-col base for this head
    const size_t rb = (size_t)b * Sc;              // token row base

    // fragment lane patterns (byte offsets)
    const uint32_t aPat = sbq +
        (uint32_t)((wrow + (lane & 15)) * PST + (lane >> 4) * 4) * 4;
    const uint32_t kPat = sbq + 2 * QLB +
        (uint32_t)(((lane & 7) + ((lane >> 4) & 1) * 8) * PST + ((lane >> 3) & 1) * 4) * 4;
    const uint32_t vPat = sbq + 4 * QLB +
        (uint32_t)(((lane & 7) + ((lane >> 3) & 1) * 8) * PST + ((lane >> 4) & 1) * 4) * 4;

    // stage Q via cp.async (waited inside first loop iteration)
    #pragma unroll
    for (int it = 0; it < 4; it++) {
        const int i   = tid + it * 128;            // 512 chunks per array
        const int row = i >> 3;
        const int c   = (i & 7) * 4;               // u32 offset
        const size_t src = (rb + qt * 64 + row) * KP2 + hb + c;
        const uint32_t dst = sbq + (uint32_t)(row * PST + c) * 4;
        CPA16(dst, Qh + src);
        CPA16(dst + QLB, Ql + src);
    }
    asm volatile("cp.async.commit_group;" ::: "memory");

    float o[8][4];
    #pragma unroll
    for (int nt = 0; nt < 8; nt++)
        #pragma unroll
        for (int e = 0; e < 4; e++) o[nt][e] = 0.f;
    float mr0 = -1e30f, mr1 = -1e30f, lr0 = 0.f, lr1 = 0.f;

    const unsigned FM = 0xffffffffu;

    for (int jt = 0; jt <= qt; jt++) {
        __syncthreads();   // previous iteration done reading K/V smem
        #pragma unroll
        for (int it = 0; it < 4; it++) {
            const int i   = tid + it * 128;
            const int row = i >> 3;
            const int c   = (i & 7) * 4;
            const size_t src = (rb + jt * 64 + row) * KP2 + hb + c;
            const uint32_t dst = sbq + (uint32_t)(row * PST + c) * 4;
            CPA16(dst + 2 * QLB, Kh + src);
            CPA16(dst + 3 * QLB, Kl + src);
            CPA16(dst + 4 * QLB, Vh + src);
            CPA16(dst + 5 * QLB, Vl + src);
        }
        asm volatile("cp.async.commit_group;" ::: "memory");
        asm volatile("cp.async.wait_group 0;" ::: "memory");
        __syncthreads();

        // S = Q @ K^T
        float s[8][4];
        #pragma unroll
        for (int nt = 0; nt < 8; nt++)
            #pragma unroll
            for (int e = 0; e < 4; e++) s[nt][e] = 0.f;

        #pragma unroll
        for (int ks = 0; ks < 4; ks++) {
            const uint32_t pbB = (uint32_t)ks * 32;
            uint32_t ah[4], al[4];
            LDM4(ah, aPat + pbB);
            LDM4(al, aPat + QLB + pbB);
            #pragma unroll
            for (int ntp = 0; ntp < 4; ntp++) {
                const uint32_t ka = kPat + (uint32_t)(ntp * 16 * PST) * 4 + pbB;
                uint32_t bh[4], bl[4];
                LDM4(bh, ka);
                LDM4(bl, ka + QLB);
                mma_bf16(s[2*ntp],   ah, bh);
                mma_bf16(s[2*ntp],   ah, bl);
                mma_bf16(s[2*ntp],   al, bh);
                mma_bf16(s[2*ntp+1], ah, bh + 2);
                mma_bf16(s[2*ntp+1], ah, bl + 2);
                mma_bf16(s[2*ntp+1], al, bh + 2);
            }
        }

        // scale + causal mask on diagonal tile
        if (jt == qt) {
            const int row0 = wrow + lq, row1 = wrow + lq + 8;
            #pragma unroll
            for (int nt = 0; nt < 8; nt++) {
                const int c0 = nt * 8 + lr * 2;
                s[nt][0] = (c0     > row0) ? -1e30f : s[nt][0] * ATT_SCALE;
                s[nt][1] = (c0 + 1 > row0) ? -1e30f : s[nt][1] * ATT_SCALE;
                s[nt][2] = (c0     > row1) ? -1e30f : s[nt][2] * ATT_SCALE;
                s[nt][3] = (c0 + 1 > row1) ? -1e30f : s[nt][3] * ATT_SCALE;
            }
        } else {
            #pragma unroll
            for (int nt = 0; nt < 8; nt++)
                #pragma unroll
                for (int e = 0; e < 4; e++) s[nt][e] *= ATT_SCALE;
        }

        // online softmax
        float mt0 = -1e30f, mt1 = -1e30f;
        #pragma unroll
        for (int nt = 0; nt < 8; nt++) {
            mt0 = fmaxf(mt0, fmaxf(s[nt][0], s[nt][1]));
            mt1 = fmaxf(mt1, fmaxf(s[nt][2], s[nt][3]));
        }
        mt0 = fmaxf(mt0, __shfl_xor_sync(FM, mt0, 1));
        mt0 = fmaxf(mt0, __shfl_xor_sync(FM, mt0, 2));
        mt1 = fmaxf(mt1, __shfl_xor_sync(FM, mt1, 1));
        mt1 = fmaxf(mt1, __shfl_xor_sync(FM, mt1, 2));
        const float mn0 = fmaxf(mr0, mt0);
        const float mn1 = fmaxf(mr1, mt1);
        const float a0 = __expf(mr0 - mn0);
        const float a1 = __expf(mr1 - mn1);
        float rs0 = 0.f, rs1 = 0.f;
        #pragma unroll
        for (int nt = 0; nt < 8; nt++) {
            s[nt][0] = __expf(s[nt][0] - mn0); rs0 += s[nt][0];
            s[nt][1] = __expf(s[nt][1] - mn0); rs0 += s[nt][1];
            s[nt][2] = __expf(s[nt][2] - mn1); rs1 += s[nt][2];
            s[nt][3] = __expf(s[nt][3] - mn1); rs1 += s[nt][3];
        }
        rs0 += __shfl_xor_sync(FM, rs0, 1);
        rs0 += __shfl_xor_sync(FM, rs0, 2);
        rs1 += __shfl_xor_sync(FM, rs1, 1);
        rs1 += __shfl_xor_sync(FM, rs1, 2);
        lr0 = lr0 * a0 + rs0; mr0 = mn0;
        lr1 = lr1 * a1 + rs1; mr1 = mn1;
        #pragma unroll
        for (int nt = 0; nt < 8; nt++) {
            o[nt][0] *= a0; o[nt][1] *= a0;
            o[nt][2] *= a1; o[nt][3] *= a1;
        }

        // O += P @ V : P from S registers, V B-fragments via ldmatrix.trans
        #pragma unroll
        for (int ks = 0; ks < 4; ks++) {
            uint32_t ph[4], pl[4];
            split_pack(s[2*ks][0],   s[2*ks][1],   ph[0], pl[0]);
            split_pack(s[2*ks][2],   s[2*ks][3],   ph[1], pl[1]);
            split_pack(s[2*ks+1][0], s[2*ks+1][1], ph[2], pl[2]);
            split_pack(s[2*ks+1][2], s[2*ks+1][3], ph[3], pl[3]);
            const uint32_t kOfs = (uint32_t)(ks * 16 * PST) * 4;
            #pragma unroll
            for (int ntp = 0; ntp < 4; ntp++) {
                const uint32_t va = vPat + kOfs + (uint32_t)(ntp * 8) * 4;
                uint32_t vh[4], vl[4];
                LDM4T(vh, va);
                LDM4T(vl, va + QLB);
                mma_bf16(o[2*ntp],   ph, vh);
                mma_bf16(o[2*ntp],   ph, vl);
                mma_bf16(o[2*ntp],   pl, vh);
                mma_bf16(o[2*ntp+1], ph, vh + 2);
                mma_bf16(o[2*ntp+1], ph, vl + 2);
                mma_bf16(o[2*ntp+1], pl, vh + 2);
            }
        }
    }

    // epilogue: normalize, write split pairs for the WO GEMM
    const float inv0 = 1.0f / lr0;
    const float inv1 = 1.0f / lr1;
    const size_t ro0 = (rb + qt * 64 + wrow + lq) * KP2 + hb;
    const size_t ro1 = ro0 + 8 * (size_t)KP2;
    #pragma unroll
    for (int nt = 0; nt < 8; nt++) {
        const int pidx = nt * 4 + lr;
        uint32_t hh, ll;
        split_pack(o[nt][0] * inv0, o[nt][1] * inv0, hh, ll);
        Ch[ro0 + pidx] = hh; Cl[ro0 + pidx] = ll;
        split_pack(o[nt][2] * inv1, o[nt][3] * inv1, hh, ll);
        Ch[ro1 + pidx] = hh; Cl[ro1 + pidx] = ll;
    }
}

// ---------------------------------------------------------------------------
extern "C" void kernel_launch(void* const* d_in, const int* in_sizes, int n_in,
                              void* d_out, int out_size) {
    (void)in_sizes; (void)n_in; (void)out_size;
    const float* x  = (const float*)d_in[0];
    const float* wq = (const float*)d_in[1];
    const float* wk = (const float*)d_in[2];
    const float* wv = (const float*)d_in[3];
    const float* wo = (const float*)d_in[4];
    float* out = (float*)d_out;

    uint32_t *xh, *xl, *qh, *ql, *kh, *kl, *vh, *vl, *ch, *cl;
    uint32_t *wqh, *wql, *wkh, *wkl, *wvh, *wvl, *woh, *wol;
    cudaGetSymbolAddress((void**)&xh,  g_xh);
    cudaGetSymbolAddress((void**)&xl,  g_xl);
    cudaGetSymbolAddress((void**)&qh,  g_qh);
    cudaGetSymbolAddress((void**)&ql,  g_ql);
    cudaGetSymbolAddress((void**)&kh,  g_kh);
    cudaGetSymbolAddress((void**)&kl,  g_kl);
    cudaGetSymbolAddress((void**)&vh,  g_vh);
    cudaGetSymbolAddress((void**)&vl,  g_vl);
    cudaGetSymbolAddress((void**)&ch,  g_ch);
    cudaGetSymbolAddress((void**)&cl,  g_cl);
    cudaGetSymbolAddress((void**)&wqh, g_wqh);
    cudaGetSymbolAddress((void**)&wql, g_wql);
    cudaGetSymbolAddress((void**)&wkh, g_wkh);
    cudaGetSymbolAddress((void**)&wkl, g_wkl);
    cudaGetSymbolAddress((void**)&wvh, g_wvh);
    cudaGetSymbolAddress((void**)&wvl, g_wvl);
    cudaGetSymbolAddress((void**)&woh, g_woh);
    cudaGetSymbolAddress((void**)&wol, g_wol);

    const int nx4 = NTOK * Ec / 4;
    const int nw4 = Ec * Ec / 4;
    split_pairs<<<nx4 / 256, 256>>>((const float4*)x,  (uint2*)xh,  (uint2*)xl,  nx4);
    split_pairs<<<nw4 / 256, 256>>>((const float4*)wq, (uint2*)wqh, (uint2*)wql, nw4);
    split_pairs<<<nw4 / 256, 256>>>((const float4*)wk, (uint2*)wkh, (uint2*)wkl, nw4);
    split_pairs<<<nw4 / 256, 256>>>((const float4*)wv, (uint2*)wvh, (uint2*)wvl, nw4);
    split_pairs<<<nw4 / 256, 256>>>((const float4*)wo, (uint2*)woh, (uint2*)wol, nw4);

    cudaFuncSetAttribute(gemm_qkv, cudaFuncAttributeMaxDynamicSharedMemorySize, GEMM_SMEM);
    cudaFuncSetAttribute(gemm_wo,  cudaFuncAttributeMaxDynamicSharedMemorySize, GEMM_SMEM);

    gemm_qkv<<<dim3(Ec / 128, NTOK / 128, 3), 256, GEMM_SMEM>>>(
        xh, xl, wqh, wql, wkh, wkl, wvh, wvl, qh, ql, kh, kl, vh, vl);

    cudaFuncSetAttribute(flash_attn_mma, cudaFuncAttributeMaxDynamicSharedMemorySize, FA_SMEM);
    flash_attn_mma<<<dim3(Sc / 64, Hc, Bc), 128, FA_SMEM>>>(qh, ql, kh, kl, vh, vl, ch, cl);

    gemm_wo<<<dim3(Ec / 128, NTOK / 128), 256, GEMM_SMEM>>>(ch, cl, woh, wol, out);
}